// round 1
// baseline (speedup 1.0000x reference)
#include <cuda_runtime.h>
#include <cuda_bf16.h>
#include <mma.h>
#include <cstdint>
#include <cstdio>

using namespace nvcuda;

#define M_TOK   16384
#define L_SEQ   4096
#define D_MODEL 1024
#define DI      2048
#define DS      16
#define DH      (DI/2)   // 1024

// ---------------- scratch (device globals; no allocation allowed) ----------
__device__ __nv_bfloat16 g_xn  [M_TOK * D_MODEL];
__device__ __nv_bfloat16 g_gate[M_TOK * DI];
__device__ __nv_bfloat16 g_val [M_TOK * DI];
__device__ __nv_bfloat16 g_ca  [M_TOK * DI];
__device__ __nv_bfloat16 g_cb  [M_TOK * DI];
__device__ __nv_bfloat16 g_y   [M_TOK * DI];
__device__ __nv_bfloat16 g_f   [M_TOK * DI];

__device__ __nv_bfloat16 g_inw  [2 * DI * D_MODEL];
__device__ __nv_bfloat16 g_fusew[DI * DI];
__device__ __nv_bfloat16 g_outw [D_MODEL * DI];
__device__ __nv_bfloat16 g_hbw  [DH * DI];
__device__ __nv_bfloat16 g_pww  [DI * DI];
__device__ __nv_bfloat16 g_Wa   [DH * DI];
__device__ __nv_bfloat16 g_Wb   [DH * DI];
__device__ float         g_T    [DS * DH];
__device__ float         g_biasb[DH];

// ---------------- fp32 -> bf16 convert ------------------------------------
__global__ void f2bf_k(const float* __restrict__ s, __nv_bfloat16* __restrict__ d, int n) {
    int i = blockIdx.x * 256 + threadIdx.x;
    if (i < n) d[i] = __float2bfloat16(s[i]);
}

// ---------------- rmsnorm ---------------------------------------------------
__global__ void rmsnorm_k(const float* __restrict__ x, const float* __restrict__ w) {
    int row = blockIdx.x;
    int tid = threadIdx.x;
    const float* xr = x + (size_t)row * D_MODEL;
    float s = 0.f;
    for (int i = tid; i < D_MODEL; i += 256) { float v = xr[i]; s += v * v; }
    __shared__ float red[256];
    red[tid] = s; __syncthreads();
    for (int o = 128; o > 0; o >>= 1) {
        if (tid < o) red[tid] += red[tid + o];
        __syncthreads();
    }
    float scale = rsqrtf(red[0] / (float)D_MODEL + 1e-6f);
    for (int i = tid; i < D_MODEL; i += 256)
        g_xn[(size_t)row * D_MODEL + i] = __float2bfloat16(xr[i] * w[i] * scale);
}

// ---------------- depthwise convs ------------------------------------------
// a = dwconv(val, k4, pad_l=1, pad_r=2):  a[l] = sum_j val[l-1+j]*k[j]
__global__ void conv_a_k(const float* __restrict__ kw, const float* __restrict__ kb) {
    size_t idx = (size_t)blockIdx.x * 256 + threadIdx.x;
    int d = (int)(idx & (DI - 1));
    size_t m = idx >> 11;
    int l = (int)(m & (L_SEQ - 1));
    float acc = kb[d];
    #pragma unroll
    for (int j = 0; j < 4; j++) {
        int ll = l - 1 + j;
        if (ll >= 0 && ll < L_SEQ)
            acc += __bfloat162float(g_val[(m + (size_t)(ll - l)) * DI + d]) * kw[d * 4 + j];
    }
    g_ca[idx] = __float2bfloat16(acc);
}

// b = silu(dwconv(val, k9, pad 4,4)): b[l] = silu( sum_j val[l-4+j]*k[j] )
__global__ void conv_b_k(const float* __restrict__ kw, const float* __restrict__ kb) {
    size_t idx = (size_t)blockIdx.x * 256 + threadIdx.x;
    int d = (int)(idx & (DI - 1));
    size_t m = idx >> 11;
    int l = (int)(m & (L_SEQ - 1));
    float acc = kb[d];
    #pragma unroll
    for (int j = 0; j < 9; j++) {
        int ll = l - 4 + j;
        if (ll >= 0 && ll < L_SEQ)
            acc += __bfloat162float(g_val[(m + (size_t)(ll - l)) * DI + d]) * kw[d * 9 + j];
    }
    float sg = 1.f / (1.f + __expf(-acc));
    g_cb[idx] = __float2bfloat16(acc * sg);
}

// ---------------- low-rank precomputes -------------------------------------
// T[s][n] = sum_d Bm[s,d] * ha_w[n,d]        (16 x 1024)
__global__ void compute_T_k(const float* __restrict__ Bm, const float* __restrict__ haw) {
    int n = blockIdx.x;         // 0..1023
    int tid = threadIdx.x;      // 128 threads
    float acc[DS];
    #pragma unroll
    for (int s = 0; s < DS; s++) acc[s] = 0.f;
    for (int d = tid; d < DI; d += 128) {
        float h = haw[(size_t)n * DI + d];
        #pragma unroll
        for (int s = 0; s < DS; s++) acc[s] += h * Bm[s * DI + d];
    }
    __shared__ float red[DS * 128];
    #pragma unroll
    for (int s = 0; s < DS; s++) red[s * 128 + tid] = acc[s];
    __syncthreads();
    if (tid < DS) {
        float t = 0.f;
        for (int i = 0; i < 128; i++) t += red[tid * 128 + i];
        g_T[tid * DH + n] = t;
    }
}

// Wa[n][k] = sum_s A[k,s] * T[s][n]          (1024 x 2048, bf16)
__global__ void compute_Wa_k(const float* __restrict__ A) {
    int idx = blockIdx.x * 256 + threadIdx.x;   // DH*DI
    int k = idx & (DI - 1);
    int n = idx >> 11;
    float acc = 0.f;
    #pragma unroll
    for (int s = 0; s < DS; s++) acc += A[k * DS + s] * g_T[s * DH + n];
    g_Wa[(size_t)n * DI + k] = __float2bfloat16(acc);
}

// bias_b[n] = hb_b[n] + sum_d hb_w[n,d]*pw_b[d]
__global__ void bias_b_k(const float* __restrict__ hbw, const float* __restrict__ pwb,
                         const float* __restrict__ hbb) {
    int n = blockIdx.x;
    int tid = threadIdx.x;
    float a = 0.f;
    for (int d = tid; d < DI; d += 256) a += hbw[(size_t)n * DI + d] * pwb[d];
    __shared__ float red[256];
    red[tid] = a; __syncthreads();
    for (int o = 128; o > 0; o >>= 1) {
        if (tid < o) red[tid] += red[tid + o];
        __syncthreads();
    }
    if (tid == 0) g_biasb[n] = red[0] + hbb[n];
}

// ---------------- generic wmma GEMM ----------------------------------------
// C[m,n] = sum_k X[m,k] * Wop[k,n]
//   BROW=false: W stored (N,K) row-major (weight layout)  -> col_major matrix_b
//   BROW=true : W stored (K,N) row-major                  -> row_major matrix_b
#define BM 128
#define BN 128
#define BK 32

enum { EPI_NONE = 0, EPI_SIG = 1, EPI_GATE = 2, EPI_RESID = 3 };

template<int EPI, bool BROW>
__global__ void __launch_bounds__(256) gemm_k(
    const __nv_bfloat16* __restrict__ X,
    const __nv_bfloat16* __restrict__ W,
    const float* __restrict__ bias,
    void* __restrict__ outp, int out_stride,
    const __nv_bfloat16* __restrict__ gate,
    const float* __restrict__ resid,
    int M, int N, int K)
{
    __shared__ alignas(32) __nv_bfloat16 As[BM * 40];
    __shared__ alignas(32) __nv_bfloat16 Bs[BROW ? (BK * 136) : (BN * 40)];

    int tid  = threadIdx.x;
    int warp = tid >> 5;
    int wm   = warp >> 1;   // 0..3
    int wn   = warp & 1;    // 0..1
    int bm = blockIdx.y * BM;
    int bn = blockIdx.x * BN;

    wmma::fragment<wmma::accumulator, 16, 16, 16, float> acc[2][4];
    #pragma unroll
    for (int i = 0; i < 2; i++)
        #pragma unroll
        for (int j = 0; j < 4; j++)
            wmma::fill_fragment(acc[i][j], 0.f);

    for (int k0 = 0; k0 < K; k0 += BK) {
        // stage A tile: BM x BK
        #pragma unroll
        for (int i = 0; i < 2; i++) {
            int id = tid + i * 256;          // 0..511
            int r = id >> 2, s = id & 3;
            *(uint4*)(&As[r * 40 + s * 8]) =
                *(const uint4*)(X + (size_t)(bm + r) * K + k0 + s * 8);
        }
        // stage B tile
        if (!BROW) {
            #pragma unroll
            for (int i = 0; i < 2; i++) {
                int id = tid + i * 256;
                int r = id >> 2, s = id & 3;
                *(uint4*)(&Bs[r * 40 + s * 8]) =
                    *(const uint4*)(W + (size_t)(bn + r) * K + k0 + s * 8);
            }
        } else {
            #pragma unroll
            for (int i = 0; i < 2; i++) {
                int id = tid + i * 256;      // 0..511 -> 32 rows x 16 segs
                int r = id >> 4, s = id & 15;
                *(uint4*)(&Bs[r * 136 + s * 8]) =
                    *(const uint4*)(W + (size_t)(k0 + r) * N + bn + s * 8);
            }
        }
        __syncthreads();

        #pragma unroll
        for (int kk = 0; kk < BK; kk += 16) {
            wmma::fragment<wmma::matrix_a, 16, 16, 16, __nv_bfloat16, wmma::row_major> af[2];
            #pragma unroll
            for (int i = 0; i < 2; i++)
                wmma::load_matrix_sync(af[i], &As[(wm * 32 + i * 16) * 40 + kk], 40);
            #pragma unroll
            for (int j = 0; j < 4; j++) {
                if (!BROW) {
                    wmma::fragment<wmma::matrix_b, 16, 16, 16, __nv_bfloat16, wmma::col_major> bf;
                    wmma::load_matrix_sync(bf, &Bs[(wn * 64 + j * 16) * 40 + kk], 40);
                    #pragma unroll
                    for (int i = 0; i < 2; i++)
                        wmma::mma_sync(acc[i][j], af[i], bf, acc[i][j]);
                } else {
                    wmma::fragment<wmma::matrix_b, 16, 16, 16, __nv_bfloat16, wmma::row_major> bf;
                    wmma::load_matrix_sync(bf, &Bs[kk * 136 + wn * 64 + j * 16], 136);
                    #pragma unroll
                    for (int i = 0; i < 2; i++)
                        wmma::mma_sync(acc[i][j], af[i], bf, acc[i][j]);
                }
            }
        }
        __syncthreads();
    }

    // epilogue: stage each 16x16 frag via smem (reuse As), apply bias/act, store
    float* stage = ((float*)As) + warp * 256;
    int lane = tid & 31;
    #pragma unroll
    for (int i = 0; i < 2; i++) {
        #pragma unroll
        for (int j = 0; j < 4; j++) {
            wmma::store_matrix_sync(stage, acc[i][j], 16, wmma::mem_row_major);
            __syncwarp();
            #pragma unroll
            for (int e = lane; e < 256; e += 32) {
                int r = e >> 4, c = e & 15;
                int gm = bm + wm * 32 + i * 16 + r;
                int gn = bn + wn * 64 + j * 16 + c;
                float v = stage[e];
                if (bias) v += bias[gn];
                if (EPI == EPI_SIG)  v = 1.f / (1.f + __expf(-v));
                if (EPI == EPI_GATE) v *= __bfloat162float(gate[(size_t)gm * DI + gn]);
                if (EPI == EPI_RESID) {
                    ((float*)outp)[(size_t)gm * out_stride + gn] = v + resid[(size_t)gm * N + gn];
                } else {
                    ((__nv_bfloat16*)outp)[(size_t)gm * out_stride + gn] = __float2bfloat16(v);
                }
            }
            __syncwarp();
        }
    }
}

// ---------------- launch ----------------------------------------------------
static void* sym_addr(const void* s) {
    void* p = nullptr;
    cudaGetSymbolAddress(&p, s);
    return p;
}

extern "C" void kernel_launch(void* const* d_in, const int* in_sizes, int n_in,
                              void* d_out, int out_size) {
    const float* x      = (const float*)d_in[0];
    const float* norm_w = (const float*)d_in[1];
    const float* in_w   = (const float*)d_in[2];
    const float* in_b   = (const float*)d_in[3];
    const float* dwa_k  = (const float*)d_in[4];
    const float* dwa_b  = (const float*)d_in[5];
    const float* A      = (const float*)d_in[6];
    const float* Bm     = (const float*)d_in[7];
    const float* sym_k  = (const float*)d_in[8];
    const float* sym_b  = (const float*)d_in[9];
    const float* pw_w   = (const float*)d_in[10];
    const float* pw_b   = (const float*)d_in[11];
    const float* ha_w   = (const float*)d_in[12];
    const float* ha_b   = (const float*)d_in[13];
    const float* hb_w   = (const float*)d_in[14];
    const float* hb_b   = (const float*)d_in[15];
    const float* fuse_w = (const float*)d_in[16];
    const float* fuse_b = (const float*)d_in[17];
    const float* out_w  = (const float*)d_in[18];
    const float* out_b  = (const float*)d_in[19];

    __nv_bfloat16* p_xn    = (__nv_bfloat16*)sym_addr(g_xn);
    __nv_bfloat16* p_gate  = (__nv_bfloat16*)sym_addr(g_gate);
    __nv_bfloat16* p_val   = (__nv_bfloat16*)sym_addr(g_val);
    __nv_bfloat16* p_ca    = (__nv_bfloat16*)sym_addr(g_ca);
    __nv_bfloat16* p_cb    = (__nv_bfloat16*)sym_addr(g_cb);
    __nv_bfloat16* p_y     = (__nv_bfloat16*)sym_addr(g_y);
    __nv_bfloat16* p_f     = (__nv_bfloat16*)sym_addr(g_f);
    __nv_bfloat16* p_inw   = (__nv_bfloat16*)sym_addr(g_inw);
    __nv_bfloat16* p_fusew = (__nv_bfloat16*)sym_addr(g_fusew);
    __nv_bfloat16* p_outw  = (__nv_bfloat16*)sym_addr(g_outw);
    __nv_bfloat16* p_hbw   = (__nv_bfloat16*)sym_addr(g_hbw);
    __nv_bfloat16* p_pww   = (__nv_bfloat16*)sym_addr(g_pww);
    __nv_bfloat16* p_Wa    = (__nv_bfloat16*)sym_addr(g_Wa);
    __nv_bfloat16* p_Wb    = (__nv_bfloat16*)sym_addr(g_Wb);
    float*         p_biasb = (float*)sym_addr(g_biasb);

    // weight converts (fp32 -> bf16)
    auto cgrid = [](int n) { return (n + 255) / 256; };
    f2bf_k<<<cgrid(2 * DI * D_MODEL), 256>>>(in_w,   p_inw,   2 * DI * D_MODEL);
    f2bf_k<<<cgrid(DI * DI), 256>>>(fuse_w, p_fusew, DI * DI);
    f2bf_k<<<cgrid(D_MODEL * DI), 256>>>(out_w,  p_outw,  D_MODEL * DI);
    f2bf_k<<<cgrid(DH * DI), 256>>>(hb_w,   p_hbw,   DH * DI);
    f2bf_k<<<cgrid(DI * DI), 256>>>(pw_w,   p_pww,   DI * DI);

    // rmsnorm
    rmsnorm_k<<<M_TOK, 256>>>(x, norm_w);

    // in_proj split into two GEMMs: gate (sigmoid) and val
    dim3 gdIn(DI / BN, M_TOK / BM);
    gemm_k<EPI_SIG,  false><<<gdIn, 256>>>(p_xn, p_inw,                     in_b,      p_gate, DI,
                                           nullptr, nullptr, M_TOK, DI, D_MODEL);
    gemm_k<EPI_NONE, false><<<gdIn, 256>>>(p_xn, p_inw + DI * D_MODEL,      in_b + DI, p_val,  DI,
                                           nullptr, nullptr, M_TOK, DI, D_MODEL);

    // depthwise convs
    int convBlocks = (M_TOK * DI) / 256;
    conv_a_k<<<convBlocks, 256>>>(dwa_k, dwa_b);
    conv_b_k<<<convBlocks, 256>>>(sym_k, sym_b);

    // precompute folded weights
    compute_T_k<<<DH, 128>>>(Bm, ha_w);
    compute_Wa_k<<<(DH * DI) / 256, 256>>>(A);
    gemm_k<EPI_NONE, true><<<dim3(DI / BN, DH / BM), 256>>>(p_hbw, p_pww, nullptr, p_Wb, DI,
                                                            nullptr, nullptr, DH, DI, DI);
    bias_b_k<<<DH, 256>>>(hb_w, pw_b, hb_b);

    // half projections -> concat into g_y
    dim3 gdH(DH / BN, M_TOK / BM);
    gemm_k<EPI_NONE, false><<<gdH, 256>>>(p_ca, p_Wa, ha_b,    p_y,      DI,
                                          nullptr, nullptr, M_TOK, DH, DI);
    gemm_k<EPI_NONE, false><<<gdH, 256>>>(p_cb, p_Wb, p_biasb, p_y + DH, DI,
                                          nullptr, nullptr, M_TOK, DH, DI);

    // fuse (+ gate multiply)
    gemm_k<EPI_GATE, false><<<dim3(DI / BN, M_TOK / BM), 256>>>(p_y, p_fusew, fuse_b, p_f, DI,
                                                                p_gate, nullptr, M_TOK, DI, DI);

    // out projection (+ residual), fp32 output
    gemm_k<EPI_RESID, false><<<dim3(D_MODEL / BN, M_TOK / BM), 256>>>(p_f, p_outw, out_b,
                                                                      d_out, D_MODEL,
                                                                      nullptr, x,
                                                                      M_TOK, D_MODEL, DI);
}

// round 3
// speedup vs baseline: 1.5401x; 1.5401x over previous
#include <cuda_runtime.h>
#include <cuda_bf16.h>
#include <cstdint>

#define M_TOK   16384
#define L_SEQ   4096
#define D_MODEL 1024
#define DI      2048
#define DS      16
#define DH      1024

// ---------------- mma.sync GEMM tiling ----------------
#define BM 128
#define BN 128
#define BK 32
#define NSTAGE 4
#define PITCH 40                      // smem row pitch in bf16 elems (80B) -> conflict-free ldmatrix
#define STAGE_BYTES (128 * PITCH * 2) // 10240 per tile (A or B)
#define SMEM_TOTAL (NSTAGE * 2 * STAGE_BYTES)  // 81920

// ---------------- scratch (device globals) ----------------
__device__ __nv_bfloat16 g_xn  [(size_t)M_TOK * D_MODEL];
__device__ __nv_bfloat16 g_gate[(size_t)M_TOK * DI];
__device__ __nv_bfloat16 g_val [(size_t)M_TOK * DI];
__device__ __nv_bfloat16 g_ca  [(size_t)M_TOK * DI];
__device__ __nv_bfloat16 g_cb  [(size_t)M_TOK * DI];
__device__ __nv_bfloat16 g_y   [(size_t)M_TOK * DI];
__device__ __nv_bfloat16 g_f   [(size_t)M_TOK * DI];

__device__ __nv_bfloat16 g_inw  [(size_t)2 * DI * D_MODEL];
__device__ __nv_bfloat16 g_fusew[(size_t)DI * DI];
__device__ __nv_bfloat16 g_outw [(size_t)D_MODEL * DI];
__device__ __nv_bfloat16 g_hbw  [(size_t)DH * DI];
__device__ __nv_bfloat16 g_pwT  [(size_t)DI * DI];
__device__ __nv_bfloat16 g_Wa   [(size_t)DH * DI];
__device__ __nv_bfloat16 g_Wb   [(size_t)DH * DI];
__device__ float         g_T    [DS * DH];
__device__ float         g_biasb[DH];

// ---------------- PTX helpers ----------------
__device__ __forceinline__ uint32_t smem_u32(const void* p) {
    uint32_t a;
    asm("{ .reg .u64 t; cvta.to.shared.u64 t, %1; cvt.u32.u64 %0, t; }" : "=r"(a) : "l"(p));
    return a;
}
__device__ __forceinline__ void cpasync16(uint32_t dst, const void* src) {
    asm volatile("cp.async.cg.shared.global [%0], [%1], 16;" :: "r"(dst), "l"(src));
}
#define CP_COMMIT() asm volatile("cp.async.commit_group;" ::: "memory")
#define CP_WAIT2()  asm volatile("cp.async.wait_group 2;" ::: "memory")
#define CP_WAIT0()  asm volatile("cp.async.wait_group 0;" ::: "memory")

__device__ __forceinline__ void ldsm4(uint32_t* r, uint32_t addr) {
    asm volatile("ldmatrix.sync.aligned.m8n8.x4.shared.b16 {%0,%1,%2,%3}, [%4];"
        : "=r"(r[0]), "=r"(r[1]), "=r"(r[2]), "=r"(r[3]) : "r"(addr));
}
__device__ __forceinline__ void ldsm2(uint32_t* r, uint32_t addr) {
    asm volatile("ldmatrix.sync.aligned.m8n8.x2.shared.b16 {%0,%1}, [%2];"
        : "=r"(r[0]), "=r"(r[1]) : "r"(addr));
}
__device__ __forceinline__ void mma16816(float* d, const uint32_t* a, const uint32_t* b) {
    asm volatile("mma.sync.aligned.m16n8k16.row.col.f32.bf16.bf16.f32 "
        "{%0,%1,%2,%3}, {%4,%5,%6,%7}, {%8,%9}, {%0,%1,%2,%3};"
        : "+f"(d[0]), "+f"(d[1]), "+f"(d[2]), "+f"(d[3])
        : "r"(a[0]), "r"(a[1]), "r"(a[2]), "r"(a[3]), "r"(b[0]), "r"(b[1]));
}

enum { EPI_NONE = 0, EPI_SIG = 1, EPI_GATE = 2, EPI_RESID = 3 };

// C[m,n] = sum_k X[m,k]*W[n,k]; X:(M,K) bf16 row-major, W:(N,K) bf16 row-major
template<int EPI>
__global__ void __launch_bounds__(256, 2) mma_gemm_k(
    const __nv_bfloat16* __restrict__ X, const __nv_bfloat16* __restrict__ W,
    const float* __restrict__ bias, void* __restrict__ outp, int out_stride,
    const __nv_bfloat16* __restrict__ gate, const float* __restrict__ resid,
    int K)
{
    extern __shared__ char smem[];
    uint32_t sA = smem_u32(smem);
    uint32_t sB = sA + NSTAGE * STAGE_BYTES;
    int tid = threadIdx.x, warp = tid >> 5, lane = tid & 31;
    int wm = warp >> 2, wn = warp & 3;           // 2 x 4 warp grid
    int bm = blockIdx.y * BM, bn = blockIdx.x * BN;
    int NC = K / BK;

    float acc[4][4][4];
    #pragma unroll
    for (int mi = 0; mi < 4; mi++)
        #pragma unroll
        for (int ni = 0; ni < 4; ni++)
            #pragma unroll
            for (int e = 0; e < 4; e++) acc[mi][ni][e] = 0.f;

    // each stage: A tile 128x32, B tile 128x32, 16B chunks, 2 per thread per tile
    auto stage_load = [&](int st, int c) {
        uint32_t a = sA + st * STAGE_BYTES;
        uint32_t b = sB + st * STAGE_BYTES;
        int k0 = c * BK;
        #pragma unroll
        for (int it = 0; it < 2; it++) {
            int id = tid + it * 256;
            int r = id >> 2, s = id & 3;
            uint32_t off = (uint32_t)(r * PITCH + s * 8) * 2;
            cpasync16(a + off, X + (size_t)(bm + r) * K + k0 + s * 8);
            cpasync16(b + off, W + (size_t)(bn + r) * K + k0 + s * 8);
        }
    };

    #pragma unroll
    for (int c = 0; c < NSTAGE - 1; c++) {
        stage_load(c, c);
        CP_COMMIT();
    }

    for (int c = 0; c < NC; c++) {
        int st = c & (NSTAGE - 1);
        CP_WAIT2();
        __syncthreads();
        if (c + NSTAGE - 1 < NC) stage_load((c + NSTAGE - 1) & (NSTAGE - 1), c + NSTAGE - 1);
        CP_COMMIT();

        uint32_t aBase = sA + st * STAGE_BYTES;
        uint32_t bBase = sB + st * STAGE_BYTES;
        #pragma unroll
        for (int kk = 0; kk < 2; kk++) {
            uint32_t af[4][4], bf[4][2];
            #pragma unroll
            for (int mi = 0; mi < 4; mi++) {
                int row = wm * 64 + mi * 16 + (lane & 15);
                ldsm4(af[mi], aBase + (uint32_t)(row * PITCH + kk * 16 + (lane >> 4) * 8) * 2);
            }
            #pragma unroll
            for (int ni = 0; ni < 4; ni++) {
                int row = wn * 32 + ni * 8 + (lane & 7);
                ldsm2(bf[ni], bBase + (uint32_t)(row * PITCH + kk * 16 + ((lane >> 3) & 1) * 8) * 2);
            }
            #pragma unroll
            for (int mi = 0; mi < 4; mi++)
                #pragma unroll
                for (int ni = 0; ni < 4; ni++)
                    mma16816(acc[mi][ni], af[mi], bf[ni]);
        }
    }
    CP_WAIT0();

    // -------- register epilogue --------
    #pragma unroll
    for (int mi = 0; mi < 4; mi++) {
        #pragma unroll
        for (int ni = 0; ni < 4; ni++) {
            int gn = bn + wn * 32 + ni * 8 + (lane & 3) * 2;
            float b0 = 0.f, b1 = 0.f;
            if (bias) { b0 = bias[gn]; b1 = bias[gn + 1]; }
            #pragma unroll
            for (int h = 0; h < 2; h++) {
                int gm = bm + wm * 64 + mi * 16 + (lane >> 2) + h * 8;
                float v0 = acc[mi][ni][h * 2 + 0] + b0;
                float v1 = acc[mi][ni][h * 2 + 1] + b1;
                if (EPI == EPI_SIG) {
                    v0 = 1.f / (1.f + __expf(-v0));
                    v1 = 1.f / (1.f + __expf(-v1));
                }
                if (EPI == EPI_GATE) {
                    __nv_bfloat162 g2 = *(const __nv_bfloat162*)(gate + (size_t)gm * DI + gn);
                    v0 *= __bfloat162float(g2.x);
                    v1 *= __bfloat162float(g2.y);
                }
                if (EPI == EPI_RESID) {
                    const float* rp = resid + (size_t)gm * out_stride + gn;
                    float* op = (float*)outp + (size_t)gm * out_stride + gn;
                    float2 r2 = *(const float2*)rp;
                    float2 o2; o2.x = v0 + r2.x; o2.y = v1 + r2.y;
                    *(float2*)op = o2;
                } else {
                    __nv_bfloat16* op = (__nv_bfloat16*)outp + (size_t)gm * out_stride + gn;
                    *(__nv_bfloat162*)op = __floats2bfloat162_rn(v0, v1);
                }
            }
        }
    }
}

// ---------------- small kernels ----------------
__global__ void f2bf_k(const float* __restrict__ s, __nv_bfloat16* __restrict__ d, int n) {
    int i = blockIdx.x * 256 + threadIdx.x;
    if (i < n) d[i] = __float2bfloat16(s[i]);
}

__global__ void rmsnorm_k(const float* __restrict__ x, const float* __restrict__ w) {
    int row = blockIdx.x;
    int tid = threadIdx.x;
    const float* xr = x + (size_t)row * D_MODEL;
    float s = 0.f;
    for (int i = tid; i < D_MODEL; i += 256) { float v = xr[i]; s += v * v; }
    __shared__ float red[256];
    red[tid] = s; __syncthreads();
    for (int o = 128; o > 0; o >>= 1) {
        if (tid < o) red[tid] += red[tid + o];
        __syncthreads();
    }
    float scale = rsqrtf(red[0] / (float)D_MODEL + 1e-6f);
    for (int i = tid; i < D_MODEL; i += 256)
        g_xn[(size_t)row * D_MODEL + i] = __float2bfloat16(xr[i] * w[i] * scale);
}

// 32x32 tiled transpose: g_pwT[c][o] = pw_w[o][c], fp32 -> bf16
__global__ void transpose_pw_k(const float* __restrict__ src) {
    __shared__ float t[32][33];
    int bx = blockIdx.x * 32, by = blockIdx.y * 32;
    int tx = threadIdx.x, ty = threadIdx.y;
    #pragma unroll
    for (int i = 0; i < 32; i += 8)
        t[ty + i][tx] = src[(size_t)(by + ty + i) * DI + bx + tx];
    __syncthreads();
    #pragma unroll
    for (int i = 0; i < 32; i += 8)
        g_pwT[(size_t)(bx + ty + i) * DI + by + tx] = __float2bfloat16(t[tx][ty + i]);
}

// fused depthwise convs: a (4-tap, pad 1,2) and b = silu(9-tap, pad 4,4)
#define CL 128
#define CD 64
__global__ void __launch_bounds__(256) conv_fused_k(
    const float* __restrict__ ka, const float* __restrict__ ba,
    const float* __restrict__ ks, const float* __restrict__ bs)
{
    __shared__ __nv_bfloat16 sv[CL + 8][CD];
    int d0 = blockIdx.x * CD;
    int l0 = blockIdx.y * CL;
    int b  = blockIdx.z;
    const __nv_bfloat16* vb = g_val + (size_t)b * L_SEQ * DI;
    int tid = threadIdx.x;
    for (int i = tid; i < (CL + 8) * 8; i += 256) {
        int r = i >> 3, s = i & 7;
        int l = l0 - 4 + r;
        uint4 v = make_uint4(0, 0, 0, 0);
        if (l >= 0 && l < L_SEQ)
            v = *(const uint4*)(vb + (size_t)l * DI + d0 + s * 8);
        *(uint4*)(&sv[r][s * 8]) = v;
    }
    __syncthreads();
    int d = tid & (CD - 1);
    int lw = tid >> 6;
    float wa[4], w9[9];
    #pragma unroll
    for (int j = 0; j < 4; j++) wa[j] = ka[(d0 + d) * 4 + j];
    #pragma unroll
    for (int j = 0; j < 9; j++) w9[j] = ks[(d0 + d) * 9 + j];
    float bav = ba[d0 + d], bsv = bs[d0 + d];
    for (int li = 0; li < CL / 4; li++) {
        int l = lw * (CL / 4) + li;
        float aa = bav, ab = bsv;
        #pragma unroll
        for (int j = 0; j < 4; j++) aa += __bfloat162float(sv[l + 3 + j][d]) * wa[j];
        #pragma unroll
        for (int j = 0; j < 9; j++) ab += __bfloat162float(sv[l + j][d]) * w9[j];
        size_t o = ((size_t)b * L_SEQ + l0 + l) * DI + d0 + d;
        g_ca[o] = __float2bfloat16(aa);
        float sg = 1.f / (1.f + __expf(-ab));
        g_cb[o] = __float2bfloat16(ab * sg);
    }
}

// T[s][n] = sum_d Bm[s,d] * ha_w[n,d]
__global__ void compute_T_k(const float* __restrict__ Bm, const float* __restrict__ haw) {
    int n = blockIdx.x;
    int tid = threadIdx.x;
    float acc[DS];
    #pragma unroll
    for (int s = 0; s < DS; s++) acc[s] = 0.f;
    for (int d = tid; d < DI; d += 128) {
        float h = haw[(size_t)n * DI + d];
        #pragma unroll
        for (int s = 0; s < DS; s++) acc[s] += h * Bm[s * DI + d];
    }
    __shared__ float red[DS * 128];
    #pragma unroll
    for (int s = 0; s < DS; s++) red[s * 128 + tid] = acc[s];
    __syncthreads();
    if (tid < DS) {
        float t = 0.f;
        for (int i = 0; i < 128; i++) t += red[tid * 128 + i];
        g_T[tid * DH + n] = t;
    }
}

// Wa[n][k] = sum_s A[k,s] * T[s][n]
__global__ void compute_Wa_k(const float* __restrict__ A) {
    int idx = blockIdx.x * 256 + threadIdx.x;
    int k = idx & (DI - 1);
    int n = idx >> 11;
    float acc = 0.f;
    #pragma unroll
    for (int s = 0; s < DS; s++) acc += A[k * DS + s] * g_T[s * DH + n];
    g_Wa[(size_t)n * DI + k] = __float2bfloat16(acc);
}

// bias_b[n] = hb_b[n] + sum_d hb_w[n,d]*pw_b[d]
__global__ void bias_b_k(const float* __restrict__ hbw, const float* __restrict__ pwb,
                         const float* __restrict__ hbb) {
    int n = blockIdx.x;
    int tid = threadIdx.x;
    float a = 0.f;
    for (int d = tid; d < DI; d += 256) a += hbw[(size_t)n * DI + d] * pwb[d];
    __shared__ float red[256];
    red[tid] = a; __syncthreads();
    for (int o = 128; o > 0; o >>= 1) {
        if (tid < o) red[tid] += red[tid + o];
        __syncthreads();
    }
    if (tid == 0) g_biasb[n] = red[0] + hbb[n];
}

// ---------------- launch ----------------
static void* sym_addr(const void* s) {
    void* p = nullptr;
    cudaGetSymbolAddress(&p, s);
    return p;
}

extern "C" void kernel_launch(void* const* d_in, const int* in_sizes, int n_in,
                              void* d_out, int out_size) {
    const float* x      = (const float*)d_in[0];
    const float* norm_w = (const float*)d_in[1];
    const float* in_w   = (const float*)d_in[2];
    const float* in_b   = (const float*)d_in[3];
    const float* dwa_k  = (const float*)d_in[4];
    const float* dwa_b  = (const float*)d_in[5];
    const float* A      = (const float*)d_in[6];
    const float* Bm     = (const float*)d_in[7];
    const float* sym_k  = (const float*)d_in[8];
    const float* sym_b  = (const float*)d_in[9];
    const float* pw_w   = (const float*)d_in[10];
    const float* pw_b   = (const float*)d_in[11];
    const float* ha_w   = (const float*)d_in[12];
    const float* ha_b   = (const float*)d_in[13];
    const float* hb_w   = (const float*)d_in[14];
    const float* hb_b   = (const float*)d_in[15];
    const float* fuse_w = (const float*)d_in[16];
    const float* fuse_b = (const float*)d_in[17];
    const float* out_w  = (const float*)d_in[18];
    const float* out_b  = (const float*)d_in[19];

    __nv_bfloat16* p_xn    = (__nv_bfloat16*)sym_addr(g_xn);
    __nv_bfloat16* p_gate  = (__nv_bfloat16*)sym_addr(g_gate);
    __nv_bfloat16* p_ca    = (__nv_bfloat16*)sym_addr(g_ca);
    __nv_bfloat16* p_cb    = (__nv_bfloat16*)sym_addr(g_cb);
    __nv_bfloat16* p_val   = (__nv_bfloat16*)sym_addr(g_val);
    __nv_bfloat16* p_y     = (__nv_bfloat16*)sym_addr(g_y);
    __nv_bfloat16* p_f     = (__nv_bfloat16*)sym_addr(g_f);
    __nv_bfloat16* p_inw   = (__nv_bfloat16*)sym_addr(g_inw);
    __nv_bfloat16* p_fusew = (__nv_bfloat16*)sym_addr(g_fusew);
    __nv_bfloat16* p_outw  = (__nv_bfloat16*)sym_addr(g_outw);
    __nv_bfloat16* p_hbw   = (__nv_bfloat16*)sym_addr(g_hbw);
    __nv_bfloat16* p_pwT   = (__nv_bfloat16*)sym_addr(g_pwT);
    __nv_bfloat16* p_Wa    = (__nv_bfloat16*)sym_addr(g_Wa);
    __nv_bfloat16* p_Wb    = (__nv_bfloat16*)sym_addr(g_Wb);
    float*         p_biasb = (float*)sym_addr(g_biasb);

    cudaFuncSetAttribute(mma_gemm_k<EPI_NONE>,  cudaFuncAttributeMaxDynamicSharedMemorySize, SMEM_TOTAL);
    cudaFuncSetAttribute(mma_gemm_k<EPI_SIG>,   cudaFuncAttributeMaxDynamicSharedMemorySize, SMEM_TOTAL);
    cudaFuncSetAttribute(mma_gemm_k<EPI_GATE>,  cudaFuncAttributeMaxDynamicSharedMemorySize, SMEM_TOTAL);
    cudaFuncSetAttribute(mma_gemm_k<EPI_RESID>, cudaFuncAttributeMaxDynamicSharedMemorySize, SMEM_TOTAL);

    auto cgrid = [](int n) { return (n + 255) / 256; };

    // launches 0..4 (so launch #5, the gate GEMM, is the one ncu -s 5 profiles)
    rmsnorm_k<<<M_TOK, 256>>>(x, norm_w);
    f2bf_k<<<cgrid(2 * DI * D_MODEL), 256>>>(in_w,   p_inw,   2 * DI * D_MODEL);
    f2bf_k<<<cgrid(DI * DI), 256>>>(fuse_w, p_fusew, DI * DI);
    f2bf_k<<<cgrid(D_MODEL * DI), 256>>>(out_w,  p_outw,  D_MODEL * DI);
    f2bf_k<<<cgrid(DH * DI), 256>>>(hb_w,   p_hbw,   DH * DI);

    // in_proj: gate (sigmoid) and val
    dim3 gdIn(DI / BN, M_TOK / BM);
    mma_gemm_k<EPI_SIG><<<gdIn, 256, SMEM_TOTAL>>>(p_xn, p_inw, in_b, p_gate, DI,
                                                   nullptr, nullptr, D_MODEL);
    mma_gemm_k<EPI_NONE><<<gdIn, 256, SMEM_TOTAL>>>(p_xn, p_inw + (size_t)DI * D_MODEL,
                                                    in_b + DI, p_val, DI,
                                                    nullptr, nullptr, D_MODEL);

    transpose_pw_k<<<dim3(DI / 32, DI / 32), dim3(32, 8)>>>(pw_w);

    conv_fused_k<<<dim3(DI / CD, L_SEQ / CL, 4), 256>>>(dwa_k, dwa_b, sym_k, sym_b);

    // folded weight precomputes
    compute_T_k<<<DH, 128>>>(Bm, ha_w);
    compute_Wa_k<<<(DH * DI) / 256, 256>>>(A);
    mma_gemm_k<EPI_NONE><<<dim3(DI / BN, DH / BM), 256, SMEM_TOTAL>>>(
        p_hbw, p_pwT, nullptr, p_Wb, DI, nullptr, nullptr, DI);
    bias_b_k<<<DH, 256>>>(hb_w, pw_b, hb_b);

    // half projections -> concat into g_y
    dim3 gdH(DH / BN, M_TOK / BM);
    mma_gemm_k<EPI_NONE><<<gdH, 256, SMEM_TOTAL>>>(p_ca, p_Wa, ha_b, p_y, DI,
                                                   nullptr, nullptr, DI);
    mma_gemm_k<EPI_NONE><<<gdH, 256, SMEM_TOTAL>>>(p_cb, p_Wb, p_biasb, p_y + DH, DI,
                                                   nullptr, nullptr, DI);

    // fuse (+ gate multiply)
    mma_gemm_k<EPI_GATE><<<dim3(DI / BN, M_TOK / BM), 256, SMEM_TOTAL>>>(
        p_y, p_fusew, fuse_b, p_f, DI, p_gate, nullptr, DI);

    // out projection (+ residual), fp32 output
    mma_gemm_k<EPI_RESID><<<dim3(D_MODEL / BN, M_TOK / BM), 256, SMEM_TOTAL>>>(
        p_f, p_outw, out_b, d_out, D_MODEL, nullptr, x, DI);
}